// round 3
// baseline (speedup 1.0000x reference)
#include <cuda_runtime.h>
#include <math.h>

// EmbeddingToExpression: per-region MLP 16 -> 5 (exact-erf GELU) -> 1
//   R=1024, C=8192, DIN=16, E=5, NREG=2048. out[c,r] f32.
//
// R3: e-split across WARPS (not lanes). Block = 256 thr = 8 warps =
// 4 regions x 2 e-slices. Each warp runs the R1-style pattern (cell per
// lane, 4x LDG.128, coalesced); slice 0 computes e{0,1,2}, slice 1
// computes e{3,4,pad(wf=0)}. Partials summed in SMEM at transpose time.
// 48 weight regs -> 3 CTAs/SM (24 warps) with near-R1 instruction count.

#define RR    1024
#define CC    8192
#define DIN   16
#define EE    5
#define CPB   256   // cells per block
#define RPB   4     // regions per block (two warps each)

__global__ __launch_bounds__(256, 3)
void e2e_kernel(const float* __restrict__ emb,
                const void*  __restrict__ oi,     // int32 or int64, detected
                const float* __restrict__ W1,     // [NREG, DIN, E]
                const float* __restrict__ b1,     // [NREG, E]
                const float* __restrict__ Wf,     // [NREG, E, 1]
                float* __restrict__ out)          // [C, R]
{
    __shared__ float s_part[2 * RPB * CPB];      // [slice][region_local][cell]
    __shared__ int   s_is64;

    // Detect regions_oi element width (values < 2048 => int64 has zero
    // high words). Probes first 256 bytes only — safe for either dtype.
    if (threadIdx.x == 0) {
        const int* w = (const int*)oi;
        int all0 = 1;
        #pragma unroll
        for (int k = 0; k < 32; k++) all0 &= (w[2 * k + 1] == 0);
        s_is64 = all0;
    }
    __syncthreads();

    const int warp  = threadIdx.x >> 5;
    const int lane  = threadIdx.x & 31;
    const int rloc  = warp >> 1;                // region within block
    const int slice = warp & 1;                 // 0: e{0,1,2}  1: e{3,4,pad}
    const int r     = blockIdx.y * RPB + rloc;
    const int c0    = blockIdx.x * CPB;

    int reg;
    if (s_is64) reg = (int)((const long long*)oi)[r];
    else        reg = ((const int*)oi)[r];

    // ---- this warp's 3-wide e-slice of weights (48 regs) ----
    const int e0 = slice * 3;
    const int e1 = e0 + 1;
    const int e2 = slice ? 4 : 2;               // pad dups e=4 on slice 1
    float w[DIN * 3];
    {
        const float* wp = W1 + (size_t)reg * (DIN * EE);
        #pragma unroll
        for (int i = 0; i < DIN; i++) {
            w[i * 3 + 0] = wp[i * EE + e0];
            w[i * 3 + 1] = wp[i * EE + e1];
            w[i * 3 + 2] = wp[i * EE + e2];
        }
    }
    const float bb0 = b1[reg * EE + e0];
    const float bb1 = b1[reg * EE + e1];
    const float bb2 = b1[reg * EE + e2];
    const float wf0 = Wf[reg * EE + e0];
    const float wf1 = Wf[reg * EE + e1];
    const float wf2 = slice ? 0.0f : Wf[reg * EE + 2];   // pad contributes 0

    // ---- stream cells: lane owns cells lane, lane+32, ... (coalesced) ----
    const float4* ep = (const float4*)(emb + ((size_t)r * CC + c0) * DIN);
    float* sp = s_part + (slice * RPB + rloc) * CPB;

    #pragma unroll
    for (int k = 0; k < CPB / 32; k++) {
        const int cl = lane + 32 * k;
        const float4* cp = ep + cl * 4;
        float4 v0 = cp[0];
        float4 v1 = cp[1];
        float4 v2 = cp[2];
        float4 v3 = cp[3];

        float h0 = bb0, h1 = bb1, h2 = bb2;
        #define ACC(V, I) \
            h0 = fmaf((V), w[(I) * 3 + 0], h0); \
            h1 = fmaf((V), w[(I) * 3 + 1], h1); \
            h2 = fmaf((V), w[(I) * 3 + 2], h2);
        ACC(v0.x, 0)  ACC(v0.y, 1)  ACC(v0.z, 2)  ACC(v0.w, 3)
        ACC(v1.x, 4)  ACC(v1.y, 5)  ACC(v1.z, 6)  ACC(v1.w, 7)
        ACC(v2.x, 8)  ACC(v2.y, 9)  ACC(v2.z,10)  ACC(v2.w,11)
        ACC(v3.x,12)  ACC(v3.y,13)  ACC(v3.z,14)  ACC(v3.w,15)
        #undef ACC

        const float kk = 0.70710678118654752f;
        float g0 = 0.5f * h0 * (1.0f + erff(h0 * kk));
        float g1 = 0.5f * h1 * (1.0f + erff(h1 * kk));
        float g2 = 0.5f * h2 * (1.0f + erff(h2 * kk));
        float acc = g0 * wf0;
        acc = fmaf(g1, wf1, acc);
        acc = fmaf(g2, wf2, acc);

        sp[cl] = acc;
    }
    __syncthreads();

    // ---- transposed write: thread t owns cell c0+t; sum the two e-slices
    //      and emit 4 region values as one float4 (16B) store. Output is
    //      32 MiB and fully L2-resident, so half-sector writes coalesce
    //      with the neighbor block's half before DRAM eviction.
    const int c = threadIdx.x;
    float4 o;
    o.x = s_part[0 * CPB + c] + s_part[(RPB + 0) * CPB + c];
    o.y = s_part[1 * CPB + c] + s_part[(RPB + 1) * CPB + c];
    o.z = s_part[2 * CPB + c] + s_part[(RPB + 2) * CPB + c];
    o.w = s_part[3 * CPB + c] + s_part[(RPB + 3) * CPB + c];

    float* op = out + (size_t)(c0 + c) * RR + (size_t)blockIdx.y * RPB;
    *(float4*)op = o;
}

extern "C" void kernel_launch(void* const* d_in, const int* in_sizes, int n_in,
                              void* d_out, int out_size)
{
    const float* emb = (const float*)d_in[0];   // [R, C, DIN] f32
    const void*  oi  = d_in[1];                 // [R] int32/int64
    const float* W1  = (const float*)d_in[2];   // [NREG, DIN, E]
    const float* b1  = (const float*)d_in[3];   // [NREG, E]
    const float* Wf  = (const float*)d_in[4];   // [NREG, E, 1]
    float* out = (float*)d_out;                 // [C, R]

    dim3 grid(CC / CPB, RR / RPB);              // (32, 256)
    e2e_kernel<<<grid, 256>>>(emb, oi, W1, b1, Wf, out);
}

// round 6
// speedup vs baseline: 1.8277x; 1.8277x over previous
#include <cuda_runtime.h>
#include <math.h>

// EmbeddingToExpression: per-region MLP 16 -> 5 (exact-erf GELU) -> 1
//   R=1024, C=8192, DIN=16, E=5, NREG=2048. out[c,r] f32.
//
// R6: cp.async staging (the R4/R5 theory) resized to fit the 48 KB
// per-block SMEM default WITHOUT cudaFuncSetAttribute (R5 failed capture
// on 56 KB total). Block = 128 thr = 4 warps = 4 regions; DEPTH=3 ring;
// all SMEM static: 4*3*2KB stage + 4KB s_out = 28 KB. 4 CTAs/SM.
// wait_group 2 keeps 2 passes/thread in flight (64 KB/SM outstanding).
// SW128 swizzle on the stage buffer -> conflict-free LDS.128 readback.

#define RR      1024
#define CC      8192
#define DIN     16
#define EE      5
#define CPB     256          // cells per block
#define RPB     4            // regions per block (one warp each)
#define PASSES  8            // CPB / 32
#define DEPTH   3            // pipeline ring depth
#define STAGE_B 2048         // 32 cells * 64 B per warp-pass

__device__ __forceinline__ unsigned sw128(unsigned o) {
    return o ^ ((o >> 3) & 0x70);          // XOR 16B-column with 128B-row
}
__device__ __forceinline__ void cp16(unsigned dst, const void* src) {
    asm volatile("cp.async.cg.shared.global [%0], [%1], 16;\n"
                 :: "r"(dst), "l"(src));
}
__device__ __forceinline__ void cp_commit() {
    asm volatile("cp.async.commit_group;\n" ::: "memory");
}
__device__ __forceinline__ void cp_wait2() {
    asm volatile("cp.async.wait_group 2;\n" ::: "memory");
}

__global__ __launch_bounds__(128, 4)
void e2e_kernel(const float* __restrict__ emb,
                const void*  __restrict__ oi,     // int32 or int64, detected
                const float* __restrict__ W1,     // [NREG, DIN, E]
                const float* __restrict__ b1,     // [NREG, E]
                const float* __restrict__ Wf,     // [NREG, E, 1]
                float* __restrict__ out)          // [C, R]
{
    __shared__ __align__(1024) char s_stage[RPB * DEPTH * STAGE_B]; // 24 KB
    __shared__ float s_out[RPB * CPB];                              // 4 KB
    __shared__ int   s_is64;

    // Detect regions_oi width (values < 2048 => int64 high words are 0).
    if (threadIdx.x == 0) {
        const int* w = (const int*)oi;
        int all0 = 1;
        #pragma unroll
        for (int k = 0; k < 32; k++) all0 &= (w[2 * k + 1] == 0);
        s_is64 = all0;
    }
    __syncthreads();

    const int warp = threadIdx.x >> 5;
    const int lane = threadIdx.x & 31;
    const int r    = blockIdx.y * RPB + warp;
    const int c0   = blockIdx.x * CPB;

    int reg;
    if (s_is64) reg = (int)((const long long*)oi)[r];
    else        reg = ((const int*)oi)[r];

    // ---- per-region weights into registers (L2-resident broadcasts) ----
    float w[DIN * EE];
    {
        const float4* wp = (const float4*)(W1 + (size_t)reg * (DIN * EE));
        #pragma unroll
        for (int q = 0; q < (DIN * EE) / 4; q++) {
            float4 v = wp[q];
            w[4 * q + 0] = v.x; w[4 * q + 1] = v.y;
            w[4 * q + 2] = v.z; w[4 * q + 3] = v.w;
        }
    }
    float bb[EE], wf[EE];
    #pragma unroll
    for (int e = 0; e < EE; e++) {
        bb[e] = b1[reg * EE + e];
        wf[e] = Wf[reg * EE + e];
    }

    // ---- cp.async staging pipeline (warp-private ring of 3 stages) ----
    const char* gsrc = (const char*)(emb + ((size_t)r * CC + c0) * DIN); // 16 KB
    char*       wbuf = s_stage + warp * (DEPTH * STAGE_B);
    const unsigned sbase = (unsigned)__cvta_generic_to_shared(wbuf);

    // prologue: passes 0..1 as groups 0..1
    #pragma unroll
    for (int g = 0; g < DEPTH - 1; g++) {
        const unsigned slot = sbase + (g % DEPTH) * STAGE_B;
        const char* s = gsrc + g * STAGE_B;
        #pragma unroll
        for (int k = 0; k < 4; k++) {
            unsigned off = k * 512 + lane * 16;
            cp16(slot + sw128(off), s + off);
        }
        cp_commit();
    }

    #pragma unroll
    for (int p = 0; p < PASSES; p++) {
        // prefetch pass p+2 (empty tail groups keep group indices aligned)
        const int g = p + DEPTH - 1;
        if (g < PASSES) {
            const unsigned slot = sbase + (g % DEPTH) * STAGE_B;
            const char* s = gsrc + g * STAGE_B;
            #pragma unroll
            for (int k = 0; k < 4; k++) {
                unsigned off = k * 512 + lane * 16;
                cp16(slot + sw128(off), s + off);
            }
        }
        cp_commit();
        cp_wait2();   // all but newest 2 groups done => pass p has landed

        // ---- compute pass p from SMEM (swizzled, conflict-free) ----
        const char* xb = wbuf + (p % DEPTH) * STAGE_B;
        float4 v0 = *(const float4*)(xb + sw128(lane * 64 + 0));
        float4 v1 = *(const float4*)(xb + sw128(lane * 64 + 16));
        float4 v2 = *(const float4*)(xb + sw128(lane * 64 + 32));
        float4 v3 = *(const float4*)(xb + sw128(lane * 64 + 48));

        float h0 = bb[0], h1 = bb[1], h2 = bb[2], h3 = bb[3], h4 = bb[4];
        #define ACC(V, I) \
            h0 = fmaf((V), w[(I) * EE + 0], h0); \
            h1 = fmaf((V), w[(I) * EE + 1], h1); \
            h2 = fmaf((V), w[(I) * EE + 2], h2); \
            h3 = fmaf((V), w[(I) * EE + 3], h3); \
            h4 = fmaf((V), w[(I) * EE + 4], h4);
        ACC(v0.x, 0)  ACC(v0.y, 1)  ACC(v0.z, 2)  ACC(v0.w, 3)
        ACC(v1.x, 4)  ACC(v1.y, 5)  ACC(v1.z, 6)  ACC(v1.w, 7)
        ACC(v2.x, 8)  ACC(v2.y, 9)  ACC(v2.z,10)  ACC(v2.w,11)
        ACC(v3.x,12)  ACC(v3.y,13)  ACC(v3.z,14)  ACC(v3.w,15)
        #undef ACC

        const float kk = 0.70710678118654752f;
        float g0 = 0.5f * h0 * (1.0f + erff(h0 * kk));
        float g1 = 0.5f * h1 * (1.0f + erff(h1 * kk));
        float g2 = 0.5f * h2 * (1.0f + erff(h2 * kk));
        float g3 = 0.5f * h3 * (1.0f + erff(h3 * kk));
        float g4 = 0.5f * h4 * (1.0f + erff(h4 * kk));
        float acc = g0 * wf[0];
        acc = fmaf(g1, wf[1], acc);
        acc = fmaf(g2, wf[2], acc);
        acc = fmaf(g3, wf[3], acc);
        acc = fmaf(g4, wf[4], acc);

        s_out[warp * CPB + (p * 32 + lane)] = acc;
    }
    __syncthreads();

    // ---- transposed write: each thread emits 2 cells x 4 regions (16B) ----
    #pragma unroll
    for (int cc = 0; cc < CPB; cc += 128) {
        const int c = cc + threadIdx.x;
        float4 o;
        o.x = s_out[0 * CPB + c];
        o.y = s_out[1 * CPB + c];
        o.z = s_out[2 * CPB + c];
        o.w = s_out[3 * CPB + c];
        float* op = out + (size_t)(c0 + c) * RR + (size_t)blockIdx.y * RPB;
        *(float4*)op = o;
    }
}

extern "C" void kernel_launch(void* const* d_in, const int* in_sizes, int n_in,
                              void* d_out, int out_size)
{
    const float* emb = (const float*)d_in[0];   // [R, C, DIN] f32
    const void*  oi  = d_in[1];                 // [R] int32/int64
    const float* W1  = (const float*)d_in[2];   // [NREG, DIN, E]
    const float* b1  = (const float*)d_in[3];   // [NREG, E]
    const float* Wf  = (const float*)d_in[4];   // [NREG, E, 1]
    float* out = (float*)d_out;                 // [C, R]

    dim3 grid(CC / CPB, RR / RPB);              // (32, 256)
    e2e_kernel<<<grid, 128>>>(emb, oi, W1, b1, Wf, out);
}

// round 7
// speedup vs baseline: 1.8682x; 1.0221x over previous
#include <cuda_runtime.h>
#include <math.h>

// EmbeddingToExpression: per-region MLP 16 -> 5 (exact-erf GELU) -> 1
//   R=1024, C=8192, DIN=16, E=5, NREG=2048. out[c,r] f32.
//
// R7 = R6 (cp.async ring, warp-per-region, weights in regs) +
//  - DEPTH 4 / wait_group 3: 96 KB/SM in flight
//  - grid dims swapped (region-group fastest): the two blocks owning the
//    two 16B halves of each 32B output sector launch adjacently -> L2
//    write-merge, kills half-sector RMW
//  - swizzled SMEM offsets hoisted out of the loops (sw128 is invariant:
//    stage stride 2048 is above the swizzle bits)
//  - GELU constants folded into weights: W1,b1 prescaled by 1/sqrt(2),
//    0.5*sqrt(2) folded into wf -> ~10 fewer instrs/cell

#define RR      1024
#define CC      8192
#define DIN     16
#define EE      5
#define CPB     256          // cells per block
#define RPB     4            // regions per block (one warp each)
#define PASSES  8            // CPB / 32
#define DEPTH   4            // pipeline ring depth
#define STAGE_B 2048         // 32 cells * 64 B per warp-pass

__device__ __forceinline__ unsigned sw128(unsigned o) {
    return o ^ ((o >> 3) & 0x70);
}
__device__ __forceinline__ void cp16(unsigned dst, const void* src) {
    asm volatile("cp.async.cg.shared.global [%0], [%1], 16;\n"
                 :: "r"(dst), "l"(src));
}
__device__ __forceinline__ void cp_commit() {
    asm volatile("cp.async.commit_group;\n" ::: "memory");
}
__device__ __forceinline__ void cp_wait3() {
    asm volatile("cp.async.wait_group 3;\n" ::: "memory");
}

__global__ __launch_bounds__(128, 4)
void e2e_kernel(const float* __restrict__ emb,
                const void*  __restrict__ oi,     // int32 or int64, detected
                const float* __restrict__ W1,     // [NREG, DIN, E]
                const float* __restrict__ b1,     // [NREG, E]
                const float* __restrict__ Wf,     // [NREG, E, 1]
                float* __restrict__ out)          // [C, R]
{
    __shared__ __align__(1024) char s_stage[RPB * DEPTH * STAGE_B]; // 32 KB
    __shared__ float s_out[RPB * CPB];                              // 4 KB
    __shared__ int   s_is64;

    // Detect regions_oi width (values < 2048 => int64 high words are 0).
    if (threadIdx.x == 0) {
        const int* w = (const int*)oi;
        int all0 = 1;
        #pragma unroll
        for (int k = 0; k < 32; k++) all0 &= (w[2 * k + 1] == 0);
        s_is64 = all0;
    }
    __syncthreads();

    const int warp = threadIdx.x >> 5;
    const int lane = threadIdx.x & 31;
    const int r    = blockIdx.x * RPB + warp;   // region group = FAST grid dim
    const int c0   = blockIdx.y * CPB;

    int reg;
    if (s_is64) reg = (int)((const long long*)oi)[r];
    else        reg = ((const int*)oi)[r];

    // ---- weights, prescaled by 1/sqrt(2) so h' = h/sqrt(2) ----
    const float KI = 0.70710678118654752f;      // 1/sqrt(2)
    const float KQ = 0.70710678118654752f;      // 0.5/KI = sqrt(2)/2
    float w[DIN * EE];
    {
        const float4* wp = (const float4*)(W1 + (size_t)reg * (DIN * EE));
        #pragma unroll
        for (int q = 0; q < (DIN * EE) / 4; q++) {
            float4 v = wp[q];
            w[4 * q + 0] = v.x * KI; w[4 * q + 1] = v.y * KI;
            w[4 * q + 2] = v.z * KI; w[4 * q + 3] = v.w * KI;
        }
    }
    float bb[EE], wq[EE];
    #pragma unroll
    for (int e = 0; e < EE; e++) {
        bb[e] = b1[reg * EE + e] * KI;
        wq[e] = Wf[reg * EE + e] * KQ;          // 0.5/KI * wf
    }

    // ---- hoisted swizzled offsets (invariant across stages/passes) ----
    const char* gsrc = (const char*)(emb + ((size_t)r * CC + c0) * DIN);
    char*       wbuf = s_stage + warp * (DEPTH * STAGE_B);
    const unsigned sbase = (unsigned)__cvta_generic_to_shared(wbuf);
    unsigned po[4], co[4];
    #pragma unroll
    for (int k = 0; k < 4; k++) {
        po[k] = sw128(k * 512 + lane * 16);     // producer dst offsets
        co[k] = sw128(lane * 64 + k * 16);      // consumer src offsets
    }
    const unsigned goff = lane * 16;

    // prologue: passes 0..2 as groups 0..2
    #pragma unroll
    for (int g = 0; g < DEPTH - 1; g++) {
        const unsigned slot = sbase + (g % DEPTH) * STAGE_B;
        const char* s = gsrc + g * STAGE_B + goff;
        cp16(slot + po[0], s);
        cp16(slot + po[1], s + 512);
        cp16(slot + po[2], s + 1024);
        cp16(slot + po[3], s + 1536);
        cp_commit();
    }

    #pragma unroll
    for (int p = 0; p < PASSES; p++) {
        const int g = p + DEPTH - 1;
        if (g < PASSES) {
            const unsigned slot = sbase + (g % DEPTH) * STAGE_B;
            const char* s = gsrc + g * STAGE_B + goff;
            cp16(slot + po[0], s);
            cp16(slot + po[1], s + 512);
            cp16(slot + po[2], s + 1024);
            cp16(slot + po[3], s + 1536);
        }
        cp_commit();
        cp_wait3();   // all but newest 3 groups done => pass p landed

        // ---- compute pass p from SMEM (conflict-free LDS.128) ----
        const char* xb = wbuf + (p % DEPTH) * STAGE_B;
        float4 v0 = *(const float4*)(xb + co[0]);
        float4 v1 = *(const float4*)(xb + co[1]);
        float4 v2 = *(const float4*)(xb + co[2]);
        float4 v3 = *(const float4*)(xb + co[3]);

        float h0 = bb[0], h1 = bb[1], h2 = bb[2], h3 = bb[3], h4 = bb[4];
        #define ACC(V, I) \
            h0 = fmaf((V), w[(I) * EE + 0], h0); \
            h1 = fmaf((V), w[(I) * EE + 1], h1); \
            h2 = fmaf((V), w[(I) * EE + 2], h2); \
            h3 = fmaf((V), w[(I) * EE + 3], h3); \
            h4 = fmaf((V), w[(I) * EE + 4], h4);
        ACC(v0.x, 0)  ACC(v0.y, 1)  ACC(v0.z, 2)  ACC(v0.w, 3)
        ACC(v1.x, 4)  ACC(v1.y, 5)  ACC(v1.z, 6)  ACC(v1.w, 7)
        ACC(v2.x, 8)  ACC(v2.y, 9)  ACC(v2.z,10)  ACC(v2.w,11)
        ACC(v3.x,12)  ACC(v3.y,13)  ACC(v3.z,14)  ACC(v3.w,15)
        #undef ACC

        // gelu(h) * wf  ==  h' * (1 + erf(h')) * (0.5/KI)*wf,  h' = h/sqrt(2)
        float acc;
        {
            float t0 = 1.0f + erff(h0);
            float t1 = 1.0f + erff(h1);
            float t2 = 1.0f + erff(h2);
            float t3 = 1.0f + erff(h3);
            float t4 = 1.0f + erff(h4);
            acc = (h0 * wq[0]) * t0;
            acc = fmaf(h1 * wq[1], t1, acc);
            acc = fmaf(h2 * wq[2], t2, acc);
            acc = fmaf(h3 * wq[3], t3, acc);
            acc = fmaf(h4 * wq[4], t4, acc);
        }

        s_out[warp * CPB + (p * 32 + lane)] = acc;
    }
    __syncthreads();

    // ---- transposed write: each thread emits 2 cells x 4 regions (16B).
    //      Adjacent blockIdx.x writes the neighboring 16B half-sector and
    //      launches adjacently -> L2 merges to full 32B sectors.
    #pragma unroll
    for (int cc = 0; cc < CPB; cc += 128) {
        const int c = cc + threadIdx.x;
        float4 o;
        o.x = s_out[0 * CPB + c];
        o.y = s_out[1 * CPB + c];
        o.z = s_out[2 * CPB + c];
        o.w = s_out[3 * CPB + c];
        float* op = out + (size_t)(c0 + c) * RR + (size_t)blockIdx.x * RPB;
        *(float4*)op = o;
    }
}

extern "C" void kernel_launch(void* const* d_in, const int* in_sizes, int n_in,
                              void* d_out, int out_size)
{
    const float* emb = (const float*)d_in[0];   // [R, C, DIN] f32
    const void*  oi  = d_in[1];                 // [R] int32/int64
    const float* W1  = (const float*)d_in[2];   // [NREG, DIN, E]
    const float* b1  = (const float*)d_in[3];   // [NREG, E]
    const float* Wf  = (const float*)d_in[4];   // [NREG, E, 1]
    float* out = (float*)d_out;                 // [C, R]

    dim3 grid(RR / RPB, CC / CPB);              // (256, 32) region-group fast
    e2e_kernel<<<grid, 128>>>(emb, oi, W1, b1, Wf, out);
}